// round 17
// baseline (speedup 1.0000x reference)
#include <cuda_runtime.h>
#include <cuda_fp16.h>
#include <cstdint>

#define CIN 128
#define KNN 16
#define NMAX 8192
#define EPS 1e-5f
#define SLOPE 0.01f
#define GRID 8
#define NCELL (GRID * GRID * GRID)
#define CELLH (1.0f / GRID)
#define PADK 136  // fp16 stride per smem row (full K); ldmatrix rows differ by 4 banks

// ---------------- scratch (static device memory; no allocations) ----------------
__device__ int   g_idx[NMAX * KNN];
__device__ int   g_cid[NMAX];
__device__ int   g_cellstart[NCELL + 1];
__device__ __align__(16) float4 g_cellpts[NMAX];
__device__ __align__(16) float g_Q[NMAX * CIN];
__device__ __align__(16) float g_K[NMAX * CIN];
__device__ __align__(16) float g_V[NMAX * CIN];
__device__ __align__(16) float g_w2[(size_t)NMAX * KNN * CIN];
__device__ float g_stat[4 * CIN];   // [0:128)=sum1 [128:256)=sq1 [256:384)=sum2 [384:512)=sq2
__device__ __align__(16) __half g_Wh[4 * CIN * CIN];   // Wq,Wk,Wv,Wl fp16

__device__ __forceinline__ int cell1(float x) {
    int c = (int)(x * (float)GRID);
    return c < 0 ? 0 : (c > GRID - 1 ? GRID - 1 : c);
}

__device__ __forceinline__ uint32_t smem_u32(const void* p) {
    uint32_t a;
    asm("{ .reg .u64 t; cvta.to.shared.u64 t, %1; cvt.u32.u64 %0, t; }" : "=r"(a) : "l"(p));
    return a;
}
__device__ __forceinline__ void cp16(uint32_t dst, const void* src) {
    asm volatile("cp.async.cg.shared.global [%0], [%1], 16;" :: "r"(dst), "l"(src));
}
#define CP_COMMIT() asm volatile("cp.async.commit_group;")
#define CP_WAIT0()  asm volatile("cp.async.wait_group 0;" ::: "memory")

__device__ __forceinline__ void ldsm4(uint32_t* r, uint32_t addr) {
    asm volatile("ldmatrix.sync.aligned.m8n8.x4.shared.b16 {%0,%1,%2,%3}, [%4];"
        : "=r"(r[0]), "=r"(r[1]), "=r"(r[2]), "=r"(r[3]) : "r"(addr));
}

__device__ __forceinline__ uint32_t pack_h2(float x0, float x1) {
    __half2 h = __floats2half2_rn(x0, x1);
    return *(uint32_t*)&h;
}

__device__ __forceinline__ void mma16816h(float* d, const uint32_t* a, const uint32_t* b) {
    asm volatile(
        "mma.sync.aligned.m16n8k16.row.col.f32.f16.f16.f32 "
        "{%0,%1,%2,%3}, {%4,%5,%6,%7}, {%8,%9}, {%0,%1,%2,%3};"
        : "+f"(d[0]), "+f"(d[1]), "+f"(d[2]), "+f"(d[3])
        : "r"(a[0]), "r"(a[1]), "r"(a[2]), "r"(a[3]), "r"(b[0]), "r"(b[1]));
}

// ---------------- k_build_w: weight fp16 conversion (8 blocks) ----------------
__global__ void __launch_bounds__(1024) k_build_w(
    const float* __restrict__ Wq, const float* __restrict__ Wk,
    const float* __restrict__ Wv, const float* __restrict__ Wl)
{
    int t = threadIdx.x;
    uint32_t* oh = (uint32_t*)g_Wh;
    int e0 = blockIdx.x * 4096;
#pragma unroll
    for (int v = 0; v < 4; v++) {
        int e = e0 + v * 1024 + t;
        int m = e >> 13;
        int off = (e & 8191) * 2;
        const float* W = (m == 0) ? Wq : (m == 1 ? Wk : (m == 2 ? Wv : Wl));
        float2 x = *(const float2*)(W + off);
        oh[e] = pack_h2(x.x, x.y);
    }
}

// ---------------- k_build_grid: grid count/scan/fill + stat zero (1 block) ------
__global__ void __launch_bounds__(1024) k_build_grid(const float* __restrict__ xyz_i, int N) {
    int t = threadIdx.x;
    __shared__ int scnt[NCELL];
    __shared__ int spre[NCELL];
    __shared__ int scur[NCELL];

    if (t < NCELL) scnt[t] = 0;
    if (t < 4 * CIN) g_stat[t] = 0.f;
    __syncthreads();

    for (int i = t; i < N; i += 1024) {
        float x = xyz_i[i * 3 + 0], y = xyz_i[i * 3 + 1], z = xyz_i[i * 3 + 2];
        int cid = (cell1(z) * GRID + cell1(y)) * GRID + cell1(x);
        g_cid[i] = cid;
        atomicAdd(&scnt[cid], 1);
    }
    __syncthreads();

    if (t < NCELL) spre[t] = scnt[t];
    __syncthreads();
    for (int o = 1; o < NCELL; o <<= 1) {
        int v = (t >= o && t < NCELL) ? spre[t - o] : 0;
        __syncthreads();
        if (t < NCELL) spre[t] += v;
        __syncthreads();
    }
    if (t < NCELL) {
        int excl = spre[t] - scnt[t];
        g_cellstart[t] = excl;
        scur[t] = excl;
    }
    if (t == NCELL - 1) g_cellstart[NCELL] = spre[NCELL - 1];
    __syncthreads();

    for (int i = t; i < N; i += 1024) {
        float x = xyz_i[i * 3 + 0], y = xyz_i[i * 3 + 1], z = xyz_i[i * 3 + 2];
        int slot = atomicAdd(&scur[g_cid[i]], 1);
        g_cellpts[slot] = make_float4(x, y, z, __int_as_float(i));
    }
}

// ---------------- serial fallback knn (exact, shell expansion) ----------------
__device__ void knn_serial(int q, float qx, float qy, float qz, int cx, int cy, int cz) {
    float bd[KNN];
    int   bi[KNN];
#pragma unroll
    for (int s = 0; s < KNN; s++) { bd[s] = 1e30f; bi[s] = -1; }
    float curmax = 1e30f;
    int maxslot = 0;
    for (int R = 0; R < GRID; R++) {
        int zlo = cz - R < 0 ? 0 : cz - R, zhi = cz + R > GRID - 1 ? GRID - 1 : cz + R;
        int ylo = cy - R < 0 ? 0 : cy - R, yhi = cy + R > GRID - 1 ? GRID - 1 : cy + R;
        int xlo = cx - R < 0 ? 0 : cx - R, xhi = cx + R > GRID - 1 ? GRID - 1 : cx + R;
        for (int zz = zlo; zz <= zhi; zz++) {
            int adz = zz - cz; adz = adz < 0 ? -adz : adz;
            for (int yy = ylo; yy <= yhi; yy++) {
                int ady = yy - cy; ady = ady < 0 ? -ady : ady;
                int rowmax = adz > ady ? adz : ady;
                for (int xx = xlo; xx <= xhi; xx++) {
                    int adx = xx - cx; adx = adx < 0 ? -adx : adx;
                    int cheb = rowmax > adx ? rowmax : adx;
                    if (cheb != R) continue;
                    int cellid = (zz * GRID + yy) * GRID + xx;
                    int s0 = g_cellstart[cellid];
                    int s1 = g_cellstart[cellid + 1];
                    for (int s = s0; s < s1; s++) {
                        float4 p = g_cellpts[s];
                        float dx = qx - p.x, dy = qy - p.y, dz = qz - p.z;
                        float d2 = fmaf(dx, dx, fmaf(dy, dy, dz * dz));
                        if (d2 < curmax) {
                            int j = __float_as_int(p.w);
#pragma unroll
                            for (int u = 0; u < KNN; u++)
                                if (u == maxslot) { bd[u] = d2; bi[u] = j; }
                            curmax = -1.f;
#pragma unroll
                            for (int u = 0; u < KNN; u++)
                                if (bd[u] > curmax) { curmax = bd[u]; maxslot = u; }
                        }
                    }
                }
            }
        }
        float reach = (float)R * CELLH;
        if (curmax <= reach * reach) break;
    }
#pragma unroll
    for (int s = 0; s < KNN; s++) g_idx[q * KNN + s] = bi[s];
}

// ---------------- warp-per-query knn + fused BN1 stats ----------------
__global__ void __launch_bounds__(256) k_knn_warp(const float* __restrict__ xyz_last, int N) {
    __shared__ int s_pre[8][12];
    __shared__ int s_s0[8][12];
    __shared__ float s_sum[128], s_sq[128];
    int w = threadIdx.x >> 5;
    int lid = threadIdx.x & 31;
    int q = (blockIdx.x * 256 + threadIdx.x) >> 5;

    if (threadIdx.x < 128) { s_sum[threadIdx.x] = 0.f; s_sq[threadIdx.x] = 0.f; }
    __syncthreads();

    bool valid = (q < N);
    if (valid) {
        float qx = xyz_last[q * 3 + 0];
        float qy = xyz_last[q * 3 + 1];
        float qz = xyz_last[q * 3 + 2];
        int cx = cell1(qx), cy = cell1(qy), cz = cell1(qz);

        int zlo = cz - 1 < 0 ? 0 : cz - 1, zhi = cz + 1 > GRID - 1 ? GRID - 1 : cz + 1;
        int ylo = cy - 1 < 0 ? 0 : cy - 1, yhi = cy + 1 > GRID - 1 ? GRID - 1 : cy + 1;
        int xlo = cx - 1 < 0 ? 0 : cx - 1, xhi = cx + 1 > GRID - 1 ? GRID - 1 : cx + 1;
        int ny = yhi - ylo + 1;
        int nrows = (zhi - zlo + 1) * ny;   // <= 9

        int s0 = 0, len = 0;
        if (lid < nrows) {
            int zz = zlo + lid / ny;
            int yy = ylo + lid % ny;
            int cbase = (zz * GRID + yy) * GRID;
            s0 = g_cellstart[cbase + xlo];
            len = g_cellstart[cbase + xhi + 1] - s0;
        }
        int pre = len;
#pragma unroll
        for (int o = 1; o < 32; o <<= 1) {
            int v = __shfl_up_sync(0xFFFFFFFFu, pre, o);
            if (lid >= o) pre += v;
        }
        int T = __shfl_sync(0xFFFFFFFFu, pre, 31);
        int myStart = pre - len;

        if (lid < 12) { s_pre[w][lid] = 0x7FFFFFFF; s_s0[w][lid] = 0; }
        __syncwarp();
        if (lid <= nrows && lid < 10) s_pre[w][lid] = myStart;
        if (lid < nrows) s_s0[w][lid] = s0;
        __syncwarp();

        float bd[KNN];
        int   bi[KNN];
#pragma unroll
        for (int s = 0; s < KNN; s++) { bd[s] = 1e30f; bi[s] = -1; }
        float curmax = 1e30f;
        int maxslot = 0;

        int niter = (T + 31) >> 5;
        for (int it = 0; it < niter; it++) {
            int c = it * 32 + lid;
            if (c < T) {
                int j = 0;
#pragma unroll
                for (int i = 1; i <= 9; i++) j += (c >= s_pre[w][i]) ? 1 : 0;
                int slot = s_s0[w][j] + (c - s_pre[w][j]);
                float4 p = g_cellpts[slot];
                float dx = qx - p.x, dy = qy - p.y, dz = qz - p.z;
                float d2 = fmaf(dx, dx, fmaf(dy, dy, dz * dz));
                if (d2 < curmax) {
                    int ji = __float_as_int(p.w);
#pragma unroll
                    for (int u = 0; u < KNN; u++)
                        if (u == maxslot) { bd[u] = d2; bi[u] = ji; }
                    curmax = -1.f;
#pragma unroll
                    for (int u = 0; u < KNN; u++)
                        if (bd[u] > curmax) { curmax = bd[u]; maxslot = u; }
                }
            }
        }

        float lmin = 1e30f;
        int lslot = 0;
#pragma unroll
        for (int s = 0; s < KNN; s++)
            if (bd[s] < lmin) { lmin = bd[s]; lslot = s; }

        float d16 = 0.f;
        int myres = -1;
        for (int r = 0; r < KNN; r++) {
            float v = lmin;
            int wl = lid;
#pragma unroll
            for (int o = 16; o; o >>= 1) {
                float ov = __shfl_xor_sync(0xFFFFFFFFu, v, o);
                int owl = __shfl_xor_sync(0xFFFFFFFFu, wl, o);
                if (ov < v || (ov == v && owl < wl)) { v = ov; wl = owl; }
            }
            int myidx = -1;
#pragma unroll
            for (int s = 0; s < KNN; s++)
                if (s == lslot) myidx = bi[s];
            int wi = __shfl_sync(0xFFFFFFFFu, myidx, wl);
            d16 = v;
            if (lid == r) myres = wi;
            if (lid == wl) {
#pragma unroll
                for (int s = 0; s < KNN; s++)
                    if (s == lslot) bd[s] = 1e30f;
                lmin = 1e30f; lslot = 0;
#pragma unroll
                for (int s = 0; s < KNN; s++)
                    if (bd[s] < lmin) { lmin = bd[s]; lslot = s; }
            }
        }

        if (d16 <= CELLH * CELLH) {
            if (lid < KNN) g_idx[q * KNN + lid] = myres;
        } else {
            if (lid == 0) knn_serial(q, qx, qy, qz, cx, cy, cz);
        }
        __syncwarp();

        // fused BN1 stats: lane owns 4 channels of query q
        {
            int cb = lid * 4;
            float4 Qv = *(const float4*)(g_Q + (size_t)q * 128 + cb);
            float S0 = 0.f, S1 = 0.f, S2 = 0.f, S3 = 0.f;
            float T0 = 0.f, T1 = 0.f, T2 = 0.f, T3 = 0.f;
#pragma unroll
            for (int k = 0; k < KNN; k++) {
                int j = g_idx[q * KNN + k];
                float4 kv = *(const float4*)(g_K + (size_t)j * 128 + cb);
                S0 += kv.x; T0 = fmaf(kv.x, kv.x, T0);
                S1 += kv.y; T1 = fmaf(kv.y, kv.y, T1);
                S2 += kv.z; T2 = fmaf(kv.z, kv.z, T2);
                S3 += kv.w; T3 = fmaf(kv.w, kv.w, T3);
            }
            atomicAdd(&s_sum[cb + 0], 16.f * Qv.x - S0);
            atomicAdd(&s_sum[cb + 1], 16.f * Qv.y - S1);
            atomicAdd(&s_sum[cb + 2], 16.f * Qv.z - S2);
            atomicAdd(&s_sum[cb + 3], 16.f * Qv.w - S3);
            atomicAdd(&s_sq[cb + 0], fmaf(16.f * Qv.x, Qv.x, fmaf(-2.f * Qv.x, S0, T0)));
            atomicAdd(&s_sq[cb + 1], fmaf(16.f * Qv.y, Qv.y, fmaf(-2.f * Qv.y, S1, T1)));
            atomicAdd(&s_sq[cb + 2], fmaf(16.f * Qv.z, Qv.z, fmaf(-2.f * Qv.z, S2, T2)));
            atomicAdd(&s_sq[cb + 3], fmaf(16.f * Qv.w, Qv.w, fmaf(-2.f * Qv.w, S3, T3)));
        }
    }
    __syncthreads();
    if (threadIdx.x < 128) {
        atomicAdd(&g_stat[threadIdx.x], s_sum[threadIdx.x]);
        atomicAdd(&g_stat[128 + threadIdx.x], s_sq[threadIdx.x]);
    }
}

// ---------------- mma.sync GEMM, fp16 single-term, single full-K pass ----------------
#define TILEB (128 * PADK * 2)            // 34816 bytes
#define SM_AH 0
#define SM_BH TILEB
#define SM_AFF (2 * TILEB)                // 256 floats
#define SM_SUM (SM_AFF + 1024)
#define SM_SQ  (SM_SUM + 512)
#define SMEM_TOTAL (SM_SQ + 512)          // ~71.7 KB -> 2 blocks/SM

__global__ void __launch_bounds__(256, 2) k_mma_gemm(
    int mode,
    const float* __restrict__ fea_i, const float* __restrict__ fea_last,
    const float* __restrict__ g1, const float* __restrict__ b1, float invc)
{
    extern __shared__ char smem[];
    int t = threadIdx.x;
    int lane = t & 31, wid = t >> 5;
    int g = lane >> 2, c4 = lane & 3;
    int wm = wid & 3, wn = wid >> 2;
    int row0 = blockIdx.x * 128;

    char* Ah = smem + SM_AH;
    char* Bh = smem + SM_BH;
    float* s_aff = (float*)(smem + SM_AFF);
    float* s_sum = (float*)(smem + SM_SUM);
    float* s_sq  = (float*)(smem + SM_SQ);

    int wsel;
    float* C;
    const float* Asrc = nullptr;
    if (mode == 0) {
        wsel = blockIdx.y;
        Asrc = (wsel == 0) ? fea_last : fea_i;
        C = (wsel == 0) ? g_Q : (wsel == 1 ? g_K : g_V);
    } else {
        wsel = 3;
        C = g_w2;
    }

    // ---- B tile via cp.async
    {
        int pr = t >> 1;
        int pch = (t & 1) * 64;
        const __half* sh = g_Wh + wsel * CIN * CIN + pr * 128 + pch;
        uint32_t dh = smem_u32(Bh + (pr * PADK + pch) * 2);
#pragma unroll
        for (int c = 0; c < 8; c++)
            cp16(dh + c * 16, sh + c * 8);
        CP_COMMIT();
    }

    if (mode == 1) {
        if (t < 128) {
            float mean = g_stat[t] * invc;
            float var  = g_stat[128 + t] * invc - mean * mean;
            float sc = g1[t] * rsqrtf(var + EPS);
            s_aff[t] = sc;
            s_aff[128 + t] = b1[t] - mean * sc;
            s_sum[t] = 0.f;
            s_sq[t]  = 0.f;
        }
        __syncthreads();
    }

    float acc[2][8][4];
#pragma unroll
    for (int mf = 0; mf < 2; mf++)
#pragma unroll
        for (int nf = 0; nf < 8; nf++)
#pragma unroll
            for (int e = 0; e < 4; e++) acc[mf][nf][e] = 0.f;

    // ---- A prep: warp-per-row, lane covers cols 4*lane..4*lane+3 (float4, full K)
    {
        int cg = 4 * lane;
        float4 sc4 = make_float4(0.f, 0.f, 0.f, 0.f);
        float4 sh4 = make_float4(0.f, 0.f, 0.f, 0.f);
        float4 qv = make_float4(0.f, 0.f, 0.f, 0.f);
        if (mode == 1) {
            sc4 = *(const float4*)&s_aff[cg];
            sh4 = *(const float4*)&s_aff[128 + cg];
            int n = (row0 >> 4) + wid;
            qv = *(const float4*)(g_Q + (size_t)n * 128 + cg);
        }
#pragma unroll
        for (int r = 0; r < 16; r++) {
            int row = wid * 16 + r;
            float x0, x1, x2, x3;
            if (mode == 0) {
                float4 av = *(const float4*)(Asrc + (size_t)(row0 + row) * 128 + cg);
                x0 = av.x; x1 = av.y; x2 = av.z; x3 = av.w;
            } else {
                int j = g_idx[row0 + row];
                float4 kv = *(const float4*)(g_K + (size_t)j * 128 + cg);
                x0 = fmaf(qv.x - kv.x, sc4.x, sh4.x);
                x1 = fmaf(qv.y - kv.y, sc4.y, sh4.y);
                x2 = fmaf(qv.z - kv.z, sc4.z, sh4.z);
                x3 = fmaf(qv.w - kv.w, sc4.w, sh4.w);
                x0 = x0 >= 0.f ? x0 : SLOPE * x0;
                x1 = x1 >= 0.f ? x1 : SLOPE * x1;
                x2 = x2 >= 0.f ? x2 : SLOPE * x2;
                x3 = x3 >= 0.f ? x3 : SLOPE * x3;
            }
            uint32_t* dst = (uint32_t*)(Ah + (row * PADK + cg) * 2);
            dst[0] = pack_h2(x0, x1);
            dst[1] = pack_h2(x2, x3);
        }
    }
    CP_WAIT0();
    __syncthreads();

    int quad = lane >> 3, lr = lane & 7;
    int aoffe = (wm * 32 + (quad & 1) * 8 + lr) * PADK + (quad >> 1) * 8;
    int boffe = (wn * 64 + (quad >> 1) * 8 + lr) * PADK + (quad & 1) * 8;
    uint32_t uAh = smem_u32(Ah);
    uint32_t uBh = smem_u32(Bh);

#pragma unroll
    for (int s = 0; s < 8; s++) {
        int ke = s * 16;
        uint32_t ah[8], bh[16];
        ldsm4(&ah[0], uAh + (aoffe + ke) * 2);
        ldsm4(&ah[4], uAh + (aoffe + 16 * PADK + ke) * 2);
#pragma unroll
        for (int j = 0; j < 4; j++)
            ldsm4(&bh[4 * j], uBh + (boffe + j * 16 * PADK + ke) * 2);
#pragma unroll
        for (int mf = 0; mf < 2; mf++)
#pragma unroll
            for (int nf = 0; nf < 8; nf++)
                mma16816h(acc[mf][nf], &ah[4 * mf], &bh[2 * nf]);
    }

    // ---- epilogue
#pragma unroll
    for (int mf = 0; mf < 2; mf++)
#pragma unroll
        for (int nf = 0; nf < 8; nf++) {
            int row = row0 + wm * 32 + mf * 16 + g;
            int col = wn * 64 + nf * 8 + 2 * c4;
            *(float2*)(C + (size_t)row * 128 + col) =
                make_float2(acc[mf][nf][0], acc[mf][nf][1]);
            *(float2*)(C + (size_t)(row + 8) * 128 + col) =
                make_float2(acc[mf][nf][2], acc[mf][nf][3]);
        }

    if (mode == 1) {
#pragma unroll
        for (int nf = 0; nf < 8; nf++) {
            int col = wn * 64 + nf * 8 + 2 * c4;
            float v00 = acc[0][nf][0], v02 = acc[0][nf][2];
            float v10 = acc[1][nf][0], v12 = acc[1][nf][2];
            atomicAdd(&s_sum[col], v00 + v02 + v10 + v12);
            atomicAdd(&s_sq[col], v00 * v00 + v02 * v02 + v10 * v10 + v12 * v12);
            float v01 = acc[0][nf][1], v03 = acc[0][nf][3];
            float v11 = acc[1][nf][1], v13 = acc[1][nf][3];
            atomicAdd(&s_sum[col + 1], v01 + v03 + v11 + v13);
            atomicAdd(&s_sq[col + 1], v01 * v01 + v03 * v03 + v11 * v11 + v13 * v13);
        }
        __syncthreads();
        if (t < 128) {
            atomicAdd(&g_stat[256 + t], s_sum[t]);
            atomicAdd(&g_stat[384 + t], s_sq[t]);
        }
    }
}

// ---------------- k_out: 4 queries per block; aff2 + leaky + softmax + V sum -------
__global__ void __launch_bounds__(512) k_out(const float* __restrict__ bv,
                      const float* __restrict__ g2, const float* __restrict__ b2,
                      float invc, float* __restrict__ out, int N) {
    int grp = threadIdx.x >> 7;            // 0..3
    int c = threadIdx.x & 127;
    int n = blockIdx.x * 4 + grp;
    __shared__ int sidx[4][KNN];
    if (c < KNN) sidx[grp][c] = g_idx[n * KNN + c];
    __syncwarp();
    asm volatile("bar.sync %0, 128;" :: "r"(grp + 1) : "memory");

    float mean2 = g_stat[256 + c] * invc;
    float var2  = g_stat[384 + c] * invc - mean2 * mean2;
    float sc2 = g2[c] * rsqrtf(var2 + EPS);
    float sh2 = b2[c] - mean2 * sc2;

    float tv[KNN];
    float m = -1e30f;
#pragma unroll
    for (int k = 0; k < KNN; k++) {
        float x = g_w2[(size_t)(n * KNN + k) * 128 + c];
        x = fmaf(x, sc2, sh2);
        x = x >= 0.f ? x : SLOPE * x;
        tv[k] = x;
        m = fmaxf(m, x);
    }
    float s = 0.f;
#pragma unroll
    for (int k = 0; k < KNN; k++) { float e = __expf(tv[k] - m); tv[k] = e; s += e; }
    float inv = 1.f / s;
    float b = bv[c];
    float acc = 0.f;
#pragma unroll
    for (int k = 0; k < KNN; k++) {
        float v = g_V[(size_t)sidx[grp][k] * 128 + c] + b;
        acc = fmaf(tv[k] * inv, v, acc);
    }
    out[(size_t)n * 128 + c] = acc;
}

// ---------------- launch ----------------
extern "C" void kernel_launch(void* const* d_in, const int* in_sizes, int n_in,
                              void* d_out, int out_size) {
    const float* fea_i    = (const float*)d_in[0];
    const float* fea_last = (const float*)d_in[1];
    const float* xyz_i    = (const float*)d_in[2];
    const float* xyz_last = (const float*)d_in[3];
    const float* Wq = (const float*)d_in[5];
    const float* Wk = (const float*)d_in[7];
    const float* Wv = (const float*)d_in[9];
    const float* bv = (const float*)d_in[10];
    const float* g1 = (const float*)d_in[11];
    const float* b1 = (const float*)d_in[12];
    const float* Wl = (const float*)d_in[13];
    const float* g2 = (const float*)d_in[15];
    const float* b2 = (const float*)d_in[16];

    int N = in_sizes[0] / CIN;
    float invc = 1.0f / (float)(N * KNN);

    cudaFuncSetAttribute(k_mma_gemm, cudaFuncAttributeMaxDynamicSharedMemorySize, SMEM_TOTAL);

    k_build_w<<<8, 1024>>>(Wq, Wk, Wv, Wl);                         // idx 0
    k_build_grid<<<1, 1024>>>(xyz_i, N);                            // idx 1

    dim3 gq(N / 128, 3);
    k_mma_gemm<<<gq, 256, SMEM_TOTAL>>>(0, fea_i, fea_last, g1, b1, invc);  // idx 2

    k_knn_warp<<<(N + 7) / 8, 256>>>(xyz_last, N);                  // idx 3 (profiled)

    k_mma_gemm<<<N * KNN / 128, 256, SMEM_TOTAL>>>(1, fea_i, fea_last, g1, b1, invc); // idx 4

    k_out<<<N / 4, 512>>>(bv, g2, b2, invc, (float*)d_out, N);      // idx 5
}